// round 16
// baseline (speedup 1.0000x reference)
#include <cuda_runtime.h>
#include <cuda_bf16.h>
#include <cstdint>
#include <math.h>

// ---------------- problem constants ----------------
#define BT     4096
#define HDIM   1024
#define VCLS   32000
#define MT     128
#define NT     256
#define KT     64                    // bf16 K elems per stage (=128B SW row)
#define KSTAGES (HDIM / KT)          // 16
#define MTILES (BT / MT)             // 32
#define NTILES (VCLS / NT)           // 125
#define GEMM_THREADS 512
#define IGNORE_IDX (-100)

// ---------------- smem layout ----------------
// 2 stages x (A 16KB + B 32KB) = 98304 B, then bias (1KB), then reduce buf (6KB)
#define STAGE_BYTES 49152
#define A_BYTES     16384
#define SM_BIAS     98304
#define SM_RED      99328            // 128 rows x 4 warpN x 3 floats = 6144 B
#define SMEM_DYN    (99328 + 6144 + 128)

// ---------------- device scratch ----------------
__device__ __align__(128) __nv_bfloat16 g_xb[(size_t)BT * HDIM];        // 8 MB
__device__ __align__(128) __nv_bfloat16 g_wb[(size_t)VCLS * HDIM];      // 64 MB
__device__ float g_pmax[(size_t)NTILES * BT];
__device__ float g_psum[(size_t)NTILES * BT];
__device__ float g_xy[BT];
__device__ float g_rowloss[BT];
__device__ float g_rowvalid[BT];
__device__ int   g_t64;              // 1 if target buffer is int64, 0 if int32

__device__ __forceinline__ int get_target(const int* t32, int r, int is64) {
    return is64 ? t32[2 * r] : t32[r];
}

// ---------------- PTX helpers (arch-generic, sm_80+) ----------------
__device__ __forceinline__ uint32_t smem_u32(const void* p) {
    uint32_t a;
    asm("{ .reg .u64 t; cvta.to.shared.u64 t, %1; cvt.u32.u64 %0, t; }" : "=r"(a) : "l"(p));
    return a;
}

__device__ __forceinline__ void cp16(uint32_t saddr, const void* gaddr) {
    asm volatile("cp.async.cg.shared.global [%0], [%1], 16;" :: "r"(saddr), "l"(gaddr));
}
__device__ __forceinline__ void cp_commit() {
    asm volatile("cp.async.commit_group;" ::: "memory");
}
template <int N>
__device__ __forceinline__ void cp_wait() {
    asm volatile("cp.async.wait_group %0;" :: "n"(N) : "memory");
}

__device__ __forceinline__ void ldsm_x4(uint32_t r[4], uint32_t addr) {
    asm volatile("ldmatrix.sync.aligned.m8n8.x4.shared.b16 {%0,%1,%2,%3}, [%4];"
        : "=r"(r[0]), "=r"(r[1]), "=r"(r[2]), "=r"(r[3]) : "r"(addr));
}

__device__ __forceinline__ void mma_bf16(float c[4], const uint32_t a[4],
                                         uint32_t b0, uint32_t b1) {
    asm volatile(
        "mma.sync.aligned.m16n8k16.row.col.f32.bf16.bf16.f32 "
        "{%0,%1,%2,%3}, {%4,%5,%6,%7}, {%8,%9}, {%0,%1,%2,%3};"
        : "+f"(c[0]), "+f"(c[1]), "+f"(c[2]), "+f"(c[3])
        : "r"(a[0]), "r"(a[1]), "r"(a[2]), "r"(a[3]), "r"(b0), "r"(b1));
}

// ---------------- kernel 1: fused fp32 -> bf16 conversion + dtype sniff ----------------
__global__ void k_conv(const float4* __restrict__ x, const float4* __restrict__ w,
                       const int* __restrict__ t32) {
    if (blockIdx.x == 0 && threadIdx.x == 0) {
        int is64 = 1;
        #pragma unroll 1
        for (int r = 0; r < 64; r++) {
            int hi = t32[2 * r + 1];
            if (hi != 0 && hi != -1) { is64 = 0; break; }
        }
        g_t64 = is64;
    }
    const int nx4 = BT * HDIM / 4;
    const int nw4 = VCLS * HDIM / 4;
    int i = blockIdx.x * blockDim.x + threadIdx.x;
    const float4* src;
    uint2* dst;
    int idx;
    if (i < nx4) { src = x; dst = reinterpret_cast<uint2*>(g_xb); idx = i; }
    else {
        idx = i - nx4;
        if (idx >= nw4) return;
        src = w; dst = reinterpret_cast<uint2*>(g_wb);
    }
    float4 v = src[idx];
    __nv_bfloat162 lo = __floats2bfloat162_rn(v.x, v.y);
    __nv_bfloat162 hi = __floats2bfloat162_rn(v.z, v.w);
    uint2 o;
    o.x = *reinterpret_cast<uint32_t*>(&lo);
    o.y = *reinterpret_cast<uint32_t*>(&hi);
    dst[idx] = o;
}

// ---------------- kernel 2: HMMA GEMM (128x256, 512 thr, 2-stage, occ 2) ----------------
__device__ __forceinline__ void load_stage(uint32_t smbase, int stage, int kc,
                                           int m0, int n0, int r_, int u_, uint32_t swu) {
    const uint32_t sA = smbase + stage * STAGE_BYTES;
    const uint32_t sB = sA + A_BYTES;
    const __nv_bfloat16* gA = g_xb + (size_t)m0 * HDIM + kc * KT;
    const __nv_bfloat16* gB = g_wb + (size_t)n0 * HDIM + kc * KT;
    // A: 128 rows x 128B   (r_ in 0..63)
    #pragma unroll
    for (int it = 0; it < 2; it++) {
        int r = r_ + it * 64;
        cp16(sA + r * 128 + swu, gA + (size_t)r * HDIM + u_ * 8);
    }
    // B: 256 rows x 128B
    #pragma unroll
    for (int it = 0; it < 4; it++) {
        int r = r_ + it * 64;
        cp16(sB + r * 128 + swu, gB + (size_t)r * HDIM + u_ * 8);
    }
    cp_commit();
}

__global__ void __launch_bounds__(GEMM_THREADS, 2)
k_gemm(const int* __restrict__ t32, const float* __restrict__ bias) {
    extern __shared__ char sm[];
    float* sbias = (float*)(sm + SM_BIAS);
    float* sred  = (float*)(sm + SM_RED);
    const uint32_t smbase = smem_u32(sm);

    const int tid  = threadIdx.x;
    const int wid  = tid >> 5;
    const int lane = tid & 31;
    const int bid  = blockIdx.x;
    const int mtile = bid % MTILES;               // consecutive bids share the B slab
    const int ntile = bid / MTILES;
    const int m0 = mtile * MT;
    const int n0 = ntile * NT;
    const int warpM = wid >> 2;                   // 4 x 4 warp grid
    const int warpN = wid & 3;
    const int wm0 = warpM * 32;                   // warp tile 32 x 64
    const int wn0 = warpN * 64;

    if (tid < NT) sbias[tid] = bias[n0 + tid];

    float c[2][8][4];
    #pragma unroll
    for (int mi = 0; mi < 2; mi++)
        #pragma unroll
        for (int ni = 0; ni < 8; ni++)
            #pragma unroll
            for (int q = 0; q < 4; q++) c[mi][ni][q] = 0.0f;

    const int r_ = tid >> 3;                      // 0..63
    const int u_ = tid & 7;                       // 0..7 16B unit
    const uint32_t swu = (uint32_t)((u_ ^ (r_ & 7)) << 4);

    // ---- prologue: stages 0, 1 ----
    load_stage(smbase, 0, 0, m0, n0, r_, u_, swu);
    load_stage(smbase, 1, 1, m0, n0, r_, u_, swu);

    const int lrow = lane & 15;
    const int lhalf = lane >> 4;

    for (int kc = 0; kc < KSTAGES; kc++) {
        // commit order is monotone, so wait<1> guarantees stage kc complete
        if (kc < KSTAGES - 1) cp_wait<1>();
        else                  cp_wait<0>();
        __syncthreads();

        const uint32_t stA = smbase + (kc & 1) * STAGE_BYTES;
        const uint32_t stB = stA + A_BYTES;
        #pragma unroll
        for (int ks = 0; ks < 4; ks++) {
            const int ku = ks * 2 + lhalf;
            const uint32_t sw = (uint32_t)((ku ^ (lrow & 7)) << 4);
            uint32_t a[2][4], b[4][4];
            ldsm_x4(a[0], stA + (wm0 + lrow) * 128 + sw);
            ldsm_x4(a[1], stA + (wm0 + 16 + lrow) * 128 + sw);
            #pragma unroll
            for (int n2 = 0; n2 < 4; n2++)
                ldsm_x4(b[n2], stB + (wn0 + n2 * 16 + lrow) * 128 + sw);
            #pragma unroll
            for (int mi = 0; mi < 2; mi++)
                #pragma unroll
                for (int ni = 0; ni < 8; ni++) {
                    const int n2 = ni >> 1, pr = ni & 1;
                    mma_bf16(c[mi][ni], a[mi], b[n2][pr], b[n2][pr + 2]);
                }
        }
        __syncthreads();   // buffer kc%2 fully consumed
        if (kc + 2 < KSTAGES)
            load_stage(smbase, kc & 1, kc + 2, m0, n0, r_, u_, swu);
    }

    // ---- register-resident softmax epilogue ----
    {
        const int lr = lane >> 2;
        const int lc = lane & 3;
        const int is64 = g_t64;
        #pragma unroll
        for (int mi = 0; mi < 2; mi++) {
            #pragma unroll
            for (int half = 0; half < 2; half++) {
                const int row = wm0 + mi * 16 + half * 8 + lr;
                const int t = get_target(t32, m0 + row, is64);
                const int tl = t - n0;
                float vals[16];
                float vmax = -INFINITY;
                float xy = 0.0f;
                #pragma unroll
                for (int ni = 0; ni < 8; ni++) {
                    #pragma unroll
                    for (int j = 0; j < 2; j++) {
                        const int col = wn0 + ni * 8 + lc * 2 + j;
                        float v = c[mi][ni][half * 2 + j] + sbias[col];
                        vals[ni * 2 + j] = v;
                        vmax = fmaxf(vmax, v);
                        if (col == tl) xy = v;
                    }
                }
                float ssum = 0.0f;
                #pragma unroll
                for (int k = 0; k < 16; k++) ssum += __expf(vals[k] - vmax);
                // combine across the 4 lanes of this row (lc = 0..3)
                #pragma unroll
                for (int o = 1; o <= 2; o <<= 1) {
                    float mo = __shfl_xor_sync(0xFFFFFFFFu, vmax, o);
                    float so = __shfl_xor_sync(0xFFFFFFFFu, ssum, o);
                    float xo = __shfl_xor_sync(0xFFFFFFFFu, xy, o);
                    float mn = fmaxf(vmax, mo);
                    ssum = ssum * __expf(vmax - mn) + so * __expf(mo - mn);
                    vmax = mn;
                    xy += xo;
                }
                if (lc == 0) {
                    float* p = sred + (row * 4 + warpN) * 3;
                    p[0] = vmax; p[1] = ssum; p[2] = xy;
                }
            }
        }
    }
    __syncthreads();

    // combine the 4 warpN quarters and store per-tile partials
    if (tid < MT) {
        const int row = tid;
        float M = -INFINITY;
        #pragma unroll
        for (int q = 0; q < 4; q++) M = fmaxf(M, sred[(row * 4 + q) * 3 + 0]);
        float S = 0.0f, xy = 0.0f;
        #pragma unroll
        for (int q = 0; q < 4; q++) {
            const float* p = sred + (row * 4 + q) * 3;
            S += p[1] * __expf(p[0] - M);
            xy += p[2];
        }
        const int grow = m0 + row;
        g_pmax[(size_t)ntile * BT + grow] = M;
        g_psum[(size_t)ntile * BT + grow] = S;
        const int t = get_target(t32, grow, g_t64);
        const int tl = t - n0;
        if (tl >= 0 && tl < NT) g_xy[grow] = xy;
    }
}

// ---------------- kernel 3: per-row combine of 125 partials ----------------
__global__ void k_rowreduce(const int* __restrict__ t32) {
    int r = blockIdx.x * blockDim.x + threadIdx.x;
    if (r >= BT) return;
    float M = -INFINITY;
    for (int i = 0; i < NTILES; i++) M = fmaxf(M, g_pmax[(size_t)i * BT + r]);
    float S = 0.0f;
    for (int i = 0; i < NTILES; i++)
        S += g_psum[(size_t)i * BT + r] * __expf(g_pmax[(size_t)i * BT + r] - M);
    const int t = get_target(t32, r, g_t64);
    float valid = (t != IGNORE_IDX) ? 1.0f : 0.0f;
    float loss = 0.0f;
    if (t != IGNORE_IDX) loss = (M + logf(S)) - g_xy[r];
    g_rowloss[r] = loss;
    g_rowvalid[r] = valid;
}

// ---------------- kernel 4: deterministic final sum ----------------
__global__ void k_final(float* __restrict__ out) {
    __shared__ float ss[256];
    __shared__ float sc[256];
    int tid = threadIdx.x;
    float s = 0.0f, cnt = 0.0f;
    for (int r = tid; r < BT; r += 256) { s += g_rowloss[r]; cnt += g_rowvalid[r]; }
    ss[tid] = s; sc[tid] = cnt;
    __syncthreads();
    for (int o = 128; o > 0; o >>= 1) {
        if (tid < o) { ss[tid] += ss[tid + o]; sc[tid] += sc[tid + o]; }
        __syncthreads();
    }
    if (tid == 0) out[0] = ss[0] / sc[0];
}

// ---------------- launch ----------------
extern "C" void kernel_launch(void* const* d_in, const int* in_sizes, int n_in,
                              void* d_out, int out_size) {
    (void)in_sizes; (void)n_in; (void)out_size;
    const float* x    = (const float*)d_in[0];
    const int*   t32  = (const int*)d_in[1];    // int32 or int64 (runtime-sniffed)
    const float* w    = (const float*)d_in[2];
    const float* bias = (const float*)d_in[3];
    float* out        = (float*)d_out;

    cudaFuncSetAttribute(k_gemm, cudaFuncAttributeMaxDynamicSharedMemorySize, SMEM_DYN);

    const int nconv = BT * HDIM / 4 + VCLS * HDIM / 4;
    k_conv<<<(nconv + 255) / 256, 256>>>((const float4*)x, (const float4*)w, t32);
    k_gemm<<<MTILES * NTILES, GEMM_THREADS, SMEM_DYN>>>(t32, bias);
    k_rowreduce<<<(BT + 255) / 256, 256>>>(t32);
    k_final<<<1, 256>>>(out);
}

// round 17
// speedup vs baseline: 3.7346x; 3.7346x over previous
#include <cuda_runtime.h>
#include <cuda_bf16.h>
#include <cstdint>
#include <math.h>

// ---------------- problem constants ----------------
#define BT     4096
#define HDIM   1024
#define VCLS   32000
#define MT     128
#define NT     128
#define KT     64                    // K elems per stage
#define KSTAGES (HDIM / KT)          // 16
#define MTILES (BT / MT)             // 32
#define NTILES (VCLS / NT)           // 250
#define GEMM_THREADS 256
#define IGNORE_IDX (-100)

// ---------------- smem layout ----------------
// 3 stages x (A 16KB + B 16KB) = 98304 B, then bias (512B), then reduce buf (3KB)
#define STAGE_BYTES 32768
#define A_BYTES     16384
#define SM_BIAS     98304
#define SM_RED      98816            // 128 rows x 2 warpN x 3 floats = 3072 B
#define SMEM_DYN    (98816 + 3072 + 128)

// ---------------- device scratch ----------------
__device__ __align__(128) __nv_bfloat16 g_xb[(size_t)BT * HDIM];        // 8 MB
__device__ __align__(128) __nv_bfloat16 g_wb[(size_t)VCLS * HDIM];      // 64 MB
__device__ float g_pmax[(size_t)NTILES * BT];
__device__ float g_psum[(size_t)NTILES * BT];
__device__ float g_xy[BT];
__device__ float g_rowloss[BT];
__device__ float g_rowvalid[BT];
__device__ int   g_t64;              // 1 if target buffer is int64, 0 if int32

__device__ __forceinline__ int get_target(const int* t32, int r, int is64) {
    return is64 ? t32[2 * r] : t32[r];
}

// ---------------- PTX helpers (arch-generic, sm_80+) ----------------
__device__ __forceinline__ uint32_t smem_u32(const void* p) {
    uint32_t a;
    asm("{ .reg .u64 t; cvta.to.shared.u64 t, %1; cvt.u32.u64 %0, t; }" : "=r"(a) : "l"(p));
    return a;
}

__device__ __forceinline__ void cp16(uint32_t saddr, const void* gaddr) {
    asm volatile("cp.async.cg.shared.global [%0], [%1], 16;" :: "r"(saddr), "l"(gaddr));
}
__device__ __forceinline__ void cp_commit() {
    asm volatile("cp.async.commit_group;" ::: "memory");
}
template <int N>
__device__ __forceinline__ void cp_wait() {
    asm volatile("cp.async.wait_group %0;" :: "n"(N) : "memory");
}

__device__ __forceinline__ void ldsm_x4(uint32_t r[4], uint32_t addr) {
    asm volatile("ldmatrix.sync.aligned.m8n8.x4.shared.b16 {%0,%1,%2,%3}, [%4];"
        : "=r"(r[0]), "=r"(r[1]), "=r"(r[2]), "=r"(r[3]) : "r"(addr));
}

__device__ __forceinline__ void mma_bf16(float c[4], const uint32_t a[4],
                                         uint32_t b0, uint32_t b1) {
    asm volatile(
        "mma.sync.aligned.m16n8k16.row.col.f32.bf16.bf16.f32 "
        "{%0,%1,%2,%3}, {%4,%5,%6,%7}, {%8,%9}, {%0,%1,%2,%3};"
        : "+f"(c[0]), "+f"(c[1]), "+f"(c[2]), "+f"(c[3])
        : "r"(a[0]), "r"(a[1]), "r"(a[2]), "r"(a[3]), "r"(b0), "r"(b1));
}

// ---------------- kernel 1: fused fp32 -> bf16 conversion + dtype sniff ----------------
__global__ void k_conv(const float4* __restrict__ x, const float4* __restrict__ w,
                       const int* __restrict__ t32) {
    if (blockIdx.x == 0 && threadIdx.x == 0) {
        int is64 = 1;
        #pragma unroll 1
        for (int r = 0; r < 64; r++) {
            int hi = t32[2 * r + 1];
            if (hi != 0 && hi != -1) { is64 = 0; break; }
        }
        g_t64 = is64;
    }
    const int nx4 = BT * HDIM / 4;
    const int nw4 = VCLS * HDIM / 4;
    int i = blockIdx.x * blockDim.x + threadIdx.x;
    const float4* src;
    uint2* dst;
    int idx;
    if (i < nx4) { src = x; dst = reinterpret_cast<uint2*>(g_xb); idx = i; }
    else {
        idx = i - nx4;
        if (idx >= nw4) return;
        src = w; dst = reinterpret_cast<uint2*>(g_wb);
    }
    float4 v = src[idx];
    __nv_bfloat162 lo = __floats2bfloat162_rn(v.x, v.y);
    __nv_bfloat162 hi = __floats2bfloat162_rn(v.z, v.w);
    uint2 o;
    o.x = *reinterpret_cast<uint32_t*>(&lo);
    o.y = *reinterpret_cast<uint32_t*>(&hi);
    dst[idx] = o;
}

// ---------------- kernel 2: HMMA GEMM (128x128, 3-stage, interleaved fills) ----------------
__device__ __forceinline__ void load_stage(uint32_t smbase, int stage, int kc,
                                           int m0, int n0, int r_, int u_, uint32_t swu) {
    const uint32_t sA = smbase + stage * STAGE_BYTES;
    const uint32_t sB = sA + A_BYTES;
    const __nv_bfloat16* gA = g_xb + (size_t)m0 * HDIM + kc * KT;
    const __nv_bfloat16* gB = g_wb + (size_t)n0 * HDIM + kc * KT;
    #pragma unroll
    for (int it = 0; it < 4; it++) {
        int r = r_ + it * 32;
        cp16(sA + r * 128 + swu, gA + (size_t)r * HDIM + u_ * 8);
        cp16(sB + r * 128 + swu, gB + (size_t)r * HDIM + u_ * 8);
    }
    cp_commit();
}

__global__ void __launch_bounds__(GEMM_THREADS, 2)
k_gemm(const int* __restrict__ t32, const float* __restrict__ bias) {
    extern __shared__ char sm[];
    float* sbias = (float*)(sm + SM_BIAS);
    float* sred  = (float*)(sm + SM_RED);
    const uint32_t smbase = smem_u32(sm);

    const int tid  = threadIdx.x;
    const int wid  = tid >> 5;
    const int lane = tid & 31;
    const int bid  = blockIdx.x;
    const int mtile = bid % MTILES;               // consecutive bids share the B slab
    const int ntile = bid / MTILES;
    const int m0 = mtile * MT;
    const int n0 = ntile * NT;
    const int warpM = wid >> 1;                   // 4 x 2 warp grid
    const int warpN = wid & 1;
    const int wm0 = warpM * 32;                   // warp tile 32 x 64
    const int wn0 = warpN * 64;

    if (tid < NT) sbias[tid] = bias[n0 + tid];

    float c[2][8][4];
    #pragma unroll
    for (int mi = 0; mi < 2; mi++)
        #pragma unroll
        for (int ni = 0; ni < 8; ni++)
            #pragma unroll
            for (int q = 0; q < 4; q++) c[mi][ni][q] = 0.0f;

    const int r_ = tid >> 3;                      // 0..31
    const int u_ = tid & 7;                       // 0..7 16B unit
    const uint32_t swu = (uint32_t)((u_ ^ (r_ & 7)) << 4);

    // prefetch this thread's 4 epilogue targets (rows wm0 + mi*16 + half*8 + lane>>2)
    const int is64 = g_t64;
    int tgt[4];
    {
        const int lr = lane >> 2;
        #pragma unroll
        for (int mi = 0; mi < 2; mi++)
            #pragma unroll
            for (int half = 0; half < 2; half++)
                tgt[mi * 2 + half] =
                    get_target(t32, m0 + wm0 + mi * 16 + half * 8 + lr, is64);
    }

    // ---- prologue: stages 0, 1 ----
    load_stage(smbase, 0, 0, m0, n0, r_, u_, swu);
    load_stage(smbase, 1, 1, m0, n0, r_, u_, swu);

    const int lrow = lane & 15;
    const int lhalf = lane >> 4;

    for (int kc = 0; kc < KSTAGES; kc++) {
        // stage kc must be complete; at most 1 newer group may stay in flight
        if (kc < KSTAGES - 1) cp_wait<1>();
        else                  cp_wait<0>();
        __syncthreads();

        // next-stage fill is interleaved into the ks loop below (issued after the
        // barrier, so the buffer it overwrites, (kc+2)%3 == (kc-1)%3, is drained)
        const bool doload = (kc + 2 < KSTAGES);
        const uint32_t nsA = smbase + ((kc + 2) % 3) * STAGE_BYTES;
        const uint32_t nsB = nsA + A_BYTES;
        const __nv_bfloat16* ngA = g_xb + (size_t)m0 * HDIM + (kc + 2) * KT;
        const __nv_bfloat16* ngB = g_wb + (size_t)n0 * HDIM + (kc + 2) * KT;

        const uint32_t stA = smbase + (kc % 3) * STAGE_BYTES;
        const uint32_t stB = stA + A_BYTES;
        #pragma unroll
        for (int ks = 0; ks < 4; ks++) {
            if (doload) {
                int r = r_ + ks * 32;
                cp16(nsA + r * 128 + swu, ngA + (size_t)r * HDIM + u_ * 8);
                cp16(nsB + r * 128 + swu, ngB + (size_t)r * HDIM + u_ * 8);
            }
            const int ku = ks * 2 + lhalf;
            const uint32_t sw = (uint32_t)((ku ^ (lrow & 7)) << 4);
            uint32_t a[2][4], b[4][4];
            ldsm_x4(a[0], stA + (wm0 + lrow) * 128 + sw);
            ldsm_x4(a[1], stA + (wm0 + 16 + lrow) * 128 + sw);
            #pragma unroll
            for (int n2 = 0; n2 < 4; n2++)
                ldsm_x4(b[n2], stB + (wn0 + n2 * 16 + lrow) * 128 + sw);
            #pragma unroll
            for (int mi = 0; mi < 2; mi++)
                #pragma unroll
                for (int ni = 0; ni < 8; ni++) {
                    const int n2 = ni >> 1, pr = ni & 1;
                    mma_bf16(c[mi][ni], a[mi], b[n2][pr], b[n2][pr + 2]);
                }
        }
        if (doload) cp_commit();
    }

    // ---- register-resident softmax epilogue ----
    {
        const int lr = lane >> 2;
        const int lc = lane & 3;
        #pragma unroll
        for (int mi = 0; mi < 2; mi++) {
            #pragma unroll
            for (int half = 0; half < 2; half++) {
                const int row = wm0 + mi * 16 + half * 8 + lr;
                const int tl = tgt[mi * 2 + half] - n0;
                float vals[16];
                float vmax = -INFINITY;
                float xy = 0.0f;
                #pragma unroll
                for (int ni = 0; ni < 8; ni++) {
                    #pragma unroll
                    for (int j = 0; j < 2; j++) {
                        const int col = wn0 + ni * 8 + lc * 2 + j;
                        float v = c[mi][ni][half * 2 + j] + sbias[col];
                        vals[ni * 2 + j] = v;
                        vmax = fmaxf(vmax, v);
                        if (col == tl) xy = v;
                    }
                }
                float ssum = 0.0f;
                #pragma unroll
                for (int k = 0; k < 16; k++) ssum += __expf(vals[k] - vmax);
                // combine across the 4 lanes of this row (lc = 0..3)
                #pragma unroll
                for (int o = 1; o <= 2; o <<= 1) {
                    float mo = __shfl_xor_sync(0xFFFFFFFFu, vmax, o);
                    float so = __shfl_xor_sync(0xFFFFFFFFu, ssum, o);
                    float xo = __shfl_xor_sync(0xFFFFFFFFu, xy, o);
                    float mn = fmaxf(vmax, mo);
                    ssum = ssum * __expf(vmax - mn) + so * __expf(mo - mn);
                    vmax = mn;
                    xy += xo;
                }
                if (lc == 0) {
                    float* p = sred + (row * 2 + warpN) * 3;
                    p[0] = vmax; p[1] = ssum; p[2] = xy;
                }
            }
        }
    }
    __syncthreads();

    // combine the two warpN halves and store per-tile partials
    if (tid < MT) {
        const int row = tid;
        const float* p0 = sred + (row * 2 + 0) * 3;
        const float* p1 = sred + (row * 2 + 1) * 3;
        float M = fmaxf(p0[0], p1[0]);
        float S = p0[1] * __expf(p0[0] - M) + p1[1] * __expf(p1[0] - M);
        float xy = p0[2] + p1[2];
        const int grow = m0 + row;
        g_pmax[(size_t)ntile * BT + grow] = M;
        g_psum[(size_t)ntile * BT + grow] = S;
        const int t = get_target(t32, grow, is64);
        const int tl = t - n0;
        if (tl >= 0 && tl < NT) g_xy[grow] = xy;
    }
}

// ---------------- kernel 3: per-row combine of 250 partials ----------------
__global__ void k_rowreduce(const int* __restrict__ t32) {
    int r = blockIdx.x * blockDim.x + threadIdx.x;
    if (r >= BT) return;
    float M = -INFINITY;
    for (int i = 0; i < NTILES; i++) M = fmaxf(M, g_pmax[(size_t)i * BT + r]);
    float S = 0.0f;
    for (int i = 0; i < NTILES; i++)
        S += g_psum[(size_t)i * BT + r] * __expf(g_pmax[(size_t)i * BT + r] - M);
    const int t = get_target(t32, r, g_t64);
    float valid = (t != IGNORE_IDX) ? 1.0f : 0.0f;
    float loss = 0.0f;
    if (t != IGNORE_IDX) loss = (M + logf(S)) - g_xy[r];
    g_rowloss[r] = loss;
    g_rowvalid[r] = valid;
}

// ---------------- kernel 4: deterministic final sum ----------------
__global__ void k_final(float* __restrict__ out) {
    __shared__ float ss[256];
    __shared__ float sc[256];
    int tid = threadIdx.x;
    float s = 0.0f, cnt = 0.0f;
    for (int r = tid; r < BT; r += 256) { s += g_rowloss[r]; cnt += g_rowvalid[r]; }
    ss[tid] = s; sc[tid] = cnt;
    __syncthreads();
    for (int o = 128; o > 0; o >>= 1) {
        if (tid < o) { ss[tid] += ss[tid + o]; sc[tid] += sc[tid + o]; }
        __syncthreads();
    }
    if (tid == 0) out[0] = ss[0] / sc[0];
}

// ---------------- launch ----------------
extern "C" void kernel_launch(void* const* d_in, const int* in_sizes, int n_in,
                              void* d_out, int out_size) {
    (void)in_sizes; (void)n_in; (void)out_size;
    const float* x    = (const float*)d_in[0];
    const int*   t32  = (const int*)d_in[1];    // int32 or int64 (runtime-sniffed)
    const float* w    = (const float*)d_in[2];
    const float* bias = (const float*)d_in[3];
    float* out        = (float*)d_out;

    cudaFuncSetAttribute(k_gemm, cudaFuncAttributeMaxDynamicSharedMemorySize, SMEM_DYN);

    const int nconv = BT * HDIM / 4 + VCLS * HDIM / 4;
    k_conv<<<(nconv + 255) / 256, 256>>>((const float4*)x, (const float4*)w, t32);
    k_gemm<<<MTILES * NTILES, GEMM_THREADS, SMEM_DYN>>>(t32, bias);
    k_rowreduce<<<(BT + 255) / 256, 256>>>(t32);
    k_final<<<1, 256>>>(out);
}